// round 5
// baseline (speedup 1.0000x reference)
#include <cuda_runtime.h>

#define MAXN 50000
#define MAXE 800000
#define HID 256
#define SCAN_B 256

// ---- device scratch (no allocs allowed) ----
__device__ float g_hs[(size_t)MAXN * HID];
__device__ float g_acc[(size_t)MAXN * HID];
__device__ float g_dinv[MAXN];
__device__ int   g_cnt[MAXN];
__device__ int   g_off[MAXN + 1];
__device__ int   g_cur[MAXN];
__device__ int   g_csr[MAXE];
__device__ int   g_bsum[(MAXN + SCAN_B - 1) / SCAN_B + 1];
__device__ float g_sum[HID];
__device__ float g_sumsq[HID];
__device__ float g_bnsc[HID];
__device__ float g_bnsh[HID];
__device__ int   g_is64;

// ---- detect edge-index width (int64 vs int32) ----
__global__ void detect_kernel(const unsigned* __restrict__ e, int E) {
    __shared__ int any;
    if (threadIdx.x == 0) any = 0;
    __syncthreads();
    int nchk = 1024; if (nchk > E) nchk = E;
    int loc = 0;
    for (int i = threadIdx.x; i < nchk; i += blockDim.x) {
        if (e[2 * i + 1] != 0u) loc = 1;
    }
    if (loc) atomicOr(&any, 1);
    __syncthreads();
    if (threadIdx.x == 0) g_is64 = (any == 0);
}

__global__ void init_kernel(int M) {
    int i = blockIdx.x * blockDim.x + threadIdx.x;
    if (i < M) g_cnt[i] = 0;
    if (i < HID) { g_sum[i] = 0.0f; g_sumsq[i] = 0.0f; }
}

__global__ void count_kernel(const void* __restrict__ e, int E) {
    int i = blockIdx.x * blockDim.x + threadIdx.x;
    if (i >= E) return;
    int d = g_is64 ? (int)((const long long*)e)[E + i] : ((const int*)e)[E + i];
    atomicAdd(&g_cnt[d], 1);
}

__global__ void scanA_kernel(int M) {
    int i = blockIdx.x * SCAN_B + threadIdx.x;
    int v = (i < M) ? g_cnt[i] : 0;
#pragma unroll
    for (int o = 16; o > 0; o >>= 1) v += __shfl_down_sync(0xffffffffu, v, o);
    __shared__ int ws[8];
    int lane = threadIdx.x & 31, warp = threadIdx.x >> 5;
    if (lane == 0) ws[warp] = v;
    __syncthreads();
    if (warp == 0) {
        int s = (lane < 8) ? ws[lane] : 0;
#pragma unroll
        for (int o = 4; o > 0; o >>= 1) s += __shfl_down_sync(0xffffffffu, s, o);
        if (lane == 0) g_bsum[blockIdx.x] = s;
    }
}

__global__ void scanB_kernel(int NB, int M) {
    int i = threadIdx.x;
    int v = (i < NB) ? g_bsum[i] : 0;
    int x = v;
#pragma unroll
    for (int o = 1; o < 32; o <<= 1) {
        int t = __shfl_up_sync(0xffffffffu, x, o);
        if ((threadIdx.x & 31) >= o) x += t;
    }
    __shared__ int ws[8];
    int lane = threadIdx.x & 31, warp = threadIdx.x >> 5;
    if (lane == 31) ws[warp] = x;
    __syncthreads();
    if (warp == 0 && lane < 8) {
        int s = ws[lane];
#pragma unroll
        for (int o = 1; o < 8; o <<= 1) {
            int t = __shfl_up_sync(0xffu, s, o);
            if (lane >= o) s += t;
        }
        ws[lane] = s;
    }
    __syncthreads();
    int incl = x + (warp > 0 ? ws[warp - 1] : 0);
    if (i < NB) g_bsum[i] = incl - v;
    if (i == NB - 1) g_off[M] = incl;
}

__global__ void scanC_kernel(int M) {
    int i = blockIdx.x * SCAN_B + threadIdx.x;
    int v = (i < M) ? g_cnt[i] : 0;
    int x = v;
#pragma unroll
    for (int o = 1; o < 32; o <<= 1) {
        int t = __shfl_up_sync(0xffffffffu, x, o);
        if ((threadIdx.x & 31) >= o) x += t;
    }
    __shared__ int ws[8];
    int lane = threadIdx.x & 31, warp = threadIdx.x >> 5;
    if (lane == 31) ws[warp] = x;
    __syncthreads();
    if (warp == 0 && lane < 8) {
        int s = ws[lane];
#pragma unroll
        for (int o = 1; o < 8; o <<= 1) {
            int t = __shfl_up_sync(0xffu, s, o);
            if (lane >= o) s += t;
        }
        ws[lane] = s;
    }
    __syncthreads();
    if (i < M) {
        int excl = x - v + (warp > 0 ? ws[warp - 1] : 0) + g_bsum[blockIdx.x];
        g_off[i] = excl;
        g_cur[i] = excl;
        g_dinv[i] = rsqrtf((float)(v + 1));
    }
}

__global__ void fill_kernel(const void* __restrict__ e, int E) {
    int i = blockIdx.x * blockDim.x + threadIdx.x;
    if (i >= E) return;
    int s, d;
    if (g_is64) {
        const long long* p = (const long long*)e;
        s = (int)p[i]; d = (int)p[E + i];
    } else {
        const int* p = (const int*)e;
        s = p[i]; d = p[E + i];
    }
    int pos = atomicAdd(&g_cur[d], 1);
    g_csr[pos] = s;
}

// ---- tf32 helpers ----
__device__ __forceinline__ void tf32_split(float x, unsigned& hi, unsigned& lo) {
    unsigned h;
    asm("cvt.rna.tf32.f32 %0, %1;" : "=r"(h) : "f"(x));
    float l = x - __uint_as_float(h);
    unsigned lw;
    asm("cvt.rna.tf32.f32 %0, %1;" : "=r"(lw) : "f"(l));
    hi = h; lo = lw;
}

__device__ __forceinline__ void mma_tf32(float* d, const unsigned* a, const unsigned* b) {
    asm volatile(
        "mma.sync.aligned.m16n8k8.row.col.f32.tf32.tf32.f32 "
        "{%0,%1,%2,%3}, {%4,%5,%6,%7}, {%8,%9}, {%0,%1,%2,%3};\n"
        : "+f"(d[0]), "+f"(d[1]), "+f"(d[2]), "+f"(d[3])
        : "r"(a[0]), "r"(a[1]), "r"(a[2]), "r"(a[3]), "r"(b[0]), "r"(b[1]));
}

// ---- tf32x3 tensor-core GEMM with PRE-SPLIT smem: C[M,256] = A[M,K] @ B[K,256].
//      Each loaded element split to tf32 hi/lo ONCE and stored; inner loop = LDS+MMA only.
//      Single smem buffer, register prefetch of next tile (loads issued under compute).
//      APPLY_BN folds y = a*bnsc[k] + bnsh[k] into the A-tile global load.
//      Block tile 128x128, 512 threads (16 warps, 32x32 warp tiles), BK=16.
template <int K, bool APPLY_BN>
__global__ void __launch_bounds__(512)
sgemm_tf32(const float* __restrict__ A, const float* __restrict__ B,
           float* __restrict__ out0, int M) {
    const int N = HID;
    __shared__ unsigned AsH[128][20], AsL[128][20];
    __shared__ unsigned BsH[16][136], BsL[16][136];
    const int tid = threadIdx.x;
    const int warpId = tid >> 5;
    const int lane = tid & 31;
    const int group = lane >> 2, tig = lane & 3;
    const int wm = (warpId & 3) * 32;
    const int wn = (warpId >> 2) * 32;
    const int rowBase = blockIdx.y * 128;
    const int colBase = blockIdx.x * 128;

    float acc[2][4][4];
#pragma unroll
    for (int mt = 0; mt < 2; mt++)
#pragma unroll
        for (int nt = 0; nt < 4; nt++)
#pragma unroll
            for (int q = 0; q < 4; q++) acc[mt][nt][q] = 0.0f;

    const int aRow = tid >> 2;           // 0..127
    const int aQ = (tid & 3) * 4;        // k-col within BK
    const int bRow = tid >> 5;           // 0..15
    const int bCol = lane * 4;           // 0..124

    int aRowG = rowBase + aRow;
    if (aRowG >= M) aRowG = M - 1;
    const float* Aptr = A + (long long)aRowG * K;

    const int NT = K / 16;
    float4 av, bv;

    // preload tile 0 into registers
    av = *(const float4*)(Aptr + aQ);
    if (APPLY_BN) {
        const float4 sc = *(const float4*)(g_bnsc + aQ);
        const float4 sh = *(const float4*)(g_bnsh + aQ);
        av.x = fmaf(av.x, sc.x, sh.x); av.y = fmaf(av.y, sc.y, sh.y);
        av.z = fmaf(av.z, sc.z, sh.z); av.w = fmaf(av.w, sc.w, sh.w);
    }
    bv = *(const float4*)(B + (long long)bRow * N + colBase + bCol);

    for (int kt = 0; kt < NT; kt++) {
        // split current tile and store hi/lo smem
        {
            unsigned h, l;
            tf32_split(av.x, h, l); AsH[aRow][aQ + 0] = h; AsL[aRow][aQ + 0] = l;
            tf32_split(av.y, h, l); AsH[aRow][aQ + 1] = h; AsL[aRow][aQ + 1] = l;
            tf32_split(av.z, h, l); AsH[aRow][aQ + 2] = h; AsL[aRow][aQ + 2] = l;
            tf32_split(av.w, h, l); AsH[aRow][aQ + 3] = h; AsL[aRow][aQ + 3] = l;
            tf32_split(bv.x, h, l); BsH[bRow][bCol + 0] = h; BsL[bRow][bCol + 0] = l;
            tf32_split(bv.y, h, l); BsH[bRow][bCol + 1] = h; BsL[bRow][bCol + 1] = l;
            tf32_split(bv.z, h, l); BsH[bRow][bCol + 2] = h; BsL[bRow][bCol + 2] = l;
            tf32_split(bv.w, h, l); BsH[bRow][bCol + 3] = h; BsL[bRow][bCol + 3] = l;
        }
        __syncthreads();

        // prefetch next tile into registers (overlaps with compute below)
        if (kt + 1 < NT) {
            const int kb = (kt + 1) * 16;
            av = *(const float4*)(Aptr + kb + aQ);
            if (APPLY_BN) {
                const float4 sc = *(const float4*)(g_bnsc + kb + aQ);
                const float4 sh = *(const float4*)(g_bnsh + kb + aQ);
                av.x = fmaf(av.x, sc.x, sh.x); av.y = fmaf(av.y, sc.y, sh.y);
                av.z = fmaf(av.z, sc.z, sh.z); av.w = fmaf(av.w, sc.w, sh.w);
            }
            bv = *(const float4*)(B + (long long)(kb + bRow) * N + colBase + bCol);
        }

#pragma unroll
        for (int ksub = 0; ksub < 2; ksub++) {
            const int k0 = ksub * 8;
            unsigned ah[2][4], al[2][4], bh[4][2], bl[4][2];
#pragma unroll
            for (int mt = 0; mt < 2; mt++) {
                const int r = wm + mt * 16 + group;
                ah[mt][0] = AsH[r][k0 + tig];         al[mt][0] = AsL[r][k0 + tig];
                ah[mt][1] = AsH[r + 8][k0 + tig];     al[mt][1] = AsL[r + 8][k0 + tig];
                ah[mt][2] = AsH[r][k0 + tig + 4];     al[mt][2] = AsL[r][k0 + tig + 4];
                ah[mt][3] = AsH[r + 8][k0 + tig + 4]; al[mt][3] = AsL[r + 8][k0 + tig + 4];
            }
#pragma unroll
            for (int nt = 0; nt < 4; nt++) {
                const int c = wn + nt * 8 + group;
                bh[nt][0] = BsH[k0 + tig][c];     bl[nt][0] = BsL[k0 + tig][c];
                bh[nt][1] = BsH[k0 + tig + 4][c]; bl[nt][1] = BsL[k0 + tig + 4][c];
            }
#pragma unroll
            for (int mt = 0; mt < 2; mt++)
#pragma unroll
                for (int nt = 0; nt < 4; nt++) {
                    mma_tf32(acc[mt][nt], ah[mt], bh[nt]);
                    mma_tf32(acc[mt][nt], al[mt], bh[nt]);
                    mma_tf32(acc[mt][nt], ah[mt], bl[nt]);
                }
        }
        __syncthreads();
    }

    // epilogue: raw stores (dinv applied in gather now)
#pragma unroll
    for (int mt = 0; mt < 2; mt++) {
        const int r0 = rowBase + wm + mt * 16 + group;
        const int r1 = r0 + 8;
#pragma unroll
        for (int nt = 0; nt < 4; nt++) {
            const int c = colBase + wn + nt * 8 + tig * 2;
            if (r0 < M) {
                float2 v; v.x = acc[mt][nt][0]; v.y = acc[mt][nt][1];
                *(float2*)(out0 + (size_t)r0 * N + c) = v;
            }
            if (r1 < M) {
                float2 v; v.x = acc[mt][nt][2]; v.y = acc[mt][nt][3];
                *(float2*)(out0 + (size_t)r1 * N + c) = v;
            }
        }
    }
}

// ---- CSR gather aggregation: one 64-thread group per dst row, float4/thread.
//      Source rows scaled by dinv[src] at use; self loop scaled by dinv[r].
template <bool L1>
__global__ void __launch_bounds__(256)
gather_kernel(const float* __restrict__ srcf, const float* __restrict__ bias,
              float* __restrict__ out, int M) {
    const int grp = threadIdx.x >> 6;
    const int f = (threadIdx.x & 63) * 4;
    const float4 bb = *(const float4*)(bias + f);
    float4 s = make_float4(0, 0, 0, 0), s2 = make_float4(0, 0, 0, 0);

    for (int r = blockIdx.x * 4 + grp; r < M; r += gridDim.x * 4) {
        int beg = g_off[r], end = g_off[r + 1];
        float dv = g_dinv[r];
        float4 sv = *(const float4*)(srcf + (size_t)r * HID + f);   // self loop
        float4 acc;
        acc.x = sv.x * dv; acc.y = sv.y * dv; acc.z = sv.z * dv; acc.w = sv.w * dv;
        int e = beg;
        for (; e + 4 <= end; e += 4) {
            int i0 = g_csr[e], i1 = g_csr[e + 1], i2 = g_csr[e + 2], i3 = g_csr[e + 3];
            float d0 = g_dinv[i0], d1 = g_dinv[i1], d2 = g_dinv[i2], d3 = g_dinv[i3];
            float4 v0 = *(const float4*)(srcf + (size_t)i0 * HID + f);
            float4 v1 = *(const float4*)(srcf + (size_t)i1 * HID + f);
            float4 v2 = *(const float4*)(srcf + (size_t)i2 * HID + f);
            float4 v3 = *(const float4*)(srcf + (size_t)i3 * HID + f);
            acc.x = fmaf(v0.x, d0, acc.x); acc.y = fmaf(v0.y, d0, acc.y);
            acc.z = fmaf(v0.z, d0, acc.z); acc.w = fmaf(v0.w, d0, acc.w);
            acc.x = fmaf(v1.x, d1, acc.x); acc.y = fmaf(v1.y, d1, acc.y);
            acc.z = fmaf(v1.z, d1, acc.z); acc.w = fmaf(v1.w, d1, acc.w);
            acc.x = fmaf(v2.x, d2, acc.x); acc.y = fmaf(v2.y, d2, acc.y);
            acc.z = fmaf(v2.z, d2, acc.z); acc.w = fmaf(v2.w, d2, acc.w);
            acc.x = fmaf(v3.x, d3, acc.x); acc.y = fmaf(v3.y, d3, acc.y);
            acc.z = fmaf(v3.z, d3, acc.z); acc.w = fmaf(v3.w, d3, acc.w);
        }
        for (; e < end; e++) {
            int i0 = g_csr[e];
            float d0 = g_dinv[i0];
            float4 v0 = *(const float4*)(srcf + (size_t)i0 * HID + f);
            acc.x = fmaf(v0.x, d0, acc.x); acc.y = fmaf(v0.y, d0, acc.y);
            acc.z = fmaf(v0.z, d0, acc.z); acc.w = fmaf(v0.w, d0, acc.w);
        }
        float4 o;
        o.x = fmaf(acc.x, dv, bb.x);
        o.y = fmaf(acc.y, dv, bb.y);
        o.z = fmaf(acc.z, dv, bb.z);
        o.w = fmaf(acc.w, dv, bb.w);
        if (L1) {
            o.x = fmaxf(o.x, 0.0f); o.y = fmaxf(o.y, 0.0f);
            o.z = fmaxf(o.z, 0.0f); o.w = fmaxf(o.w, 0.0f);
            s.x += o.x; s.y += o.y; s.z += o.z; s.w += o.w;
            s2.x += o.x * o.x; s2.y += o.y * o.y;
            s2.z += o.z * o.z; s2.w += o.w * o.w;
        }
        *(float4*)(out + (size_t)r * HID + f) = o;
    }
    if (L1) {
        atomicAdd(&g_sum[f + 0], s.x);  atomicAdd(&g_sum[f + 1], s.y);
        atomicAdd(&g_sum[f + 2], s.z);  atomicAdd(&g_sum[f + 3], s.w);
        atomicAdd(&g_sumsq[f + 0], s2.x); atomicAdd(&g_sumsq[f + 1], s2.y);
        atomicAdd(&g_sumsq[f + 2], s2.z); atomicAdd(&g_sumsq[f + 3], s2.w);
    }
}

__global__ void bn_finalize(const float* __restrict__ gamma, const float* __restrict__ beta,
                            float invM) {
    int f = threadIdx.x;
    float mean = g_sum[f] * invM;
    float var = fmaf(-mean, mean, g_sumsq[f] * invM);
    float rstd = rsqrtf(var + 1e-5f);
    float sc = gamma[f] * rstd;
    g_bnsc[f] = sc;
    g_bnsh[f] = fmaf(-mean, sc, beta[f]);
}

extern "C" void kernel_launch(void* const* d_in, const int* in_sizes, int n_in,
                              void* d_out, int out_size) {
    const float* x     = (const float*)d_in[0];
    const void*  eidx  = d_in[1];
    const float* W1    = (const float*)d_in[2];
    const float* b1    = (const float*)d_in[3];
    const float* gamma = (const float*)d_in[4];
    const float* beta  = (const float*)d_in[5];
    const float* W2    = (const float*)d_in[6];
    const float* b2    = (const float*)d_in[7];
    float* out = (float*)d_out;

    const int Kin = 128;
    const int M = in_sizes[0] / Kin;     // 50000
    const int E = in_sizes[1] / 2;       // 800000
    const int NB = (M + SCAN_B - 1) / SCAN_B;

    float *hs, *acc;
    cudaGetSymbolAddress((void**)&hs, g_hs);
    cudaGetSymbolAddress((void**)&acc, g_acc);

    dim3 gemm_grid(HID / 128, (M + 127) / 128);

    detect_kernel<<<1, 256>>>((const unsigned*)eidx, E);
    init_kernel<<<(M + 255) / 256, 256>>>(M);
    count_kernel<<<(E + 255) / 256, 256>>>(eidx, E);
    // 4th launch -> ncu captures this one: layer-1 GEMM (no graph deps now)
    sgemm_tf32<128, false><<<gemm_grid, 512>>>(x, W1, hs, M);
    scanA_kernel<<<NB, SCAN_B>>>(M);
    scanB_kernel<<<1, 256>>>(NB, M);
    scanC_kernel<<<NB, SCAN_B>>>(M);
    fill_kernel<<<(E + 255) / 256, 256>>>(eidx, E);

    // gather + dinv scaling + relu + bias + BN stats -> acc
    gather_kernel<true><<<2960, 256>>>(hs, b1, acc, M);
    bn_finalize<<<1, 256>>>(gamma, beta, 1.0f / (float)M);

    // layer 2: BN folded into A-load -> hs
    sgemm_tf32<256, true><<<gemm_grid, 512>>>(acc, W2, hs, M);
    // gather + bias -> d_out
    gather_kernel<false><<<2960, 256>>>(hs, b2, out, M);
}